// round 15
// baseline (speedup 1.0000x reference)
#include <cuda_runtime.h>
#include <cstdint>

#define NS 65536
#define D  32
#define R  128

typedef unsigned long long ull;

// pair tables, [d][64 pairs]:
//   gWV4: float4 (w0, w1, v0, v1) — 16B/record, d-stride 1024B
//   gC2:  float2 (c0, c1)         —  8B/record, d-stride 512B
__device__ float4 gWV4[D * 64];
__device__ float2 gC2[D * 64];
__device__ float2 gB2[64];

__global__ void anfis_precomp(const float* __restrict__ a,
                              const float* __restrict__ b,
                              const float* __restrict__ c) {
    int r = blockIdx.x, d = threadIdx.x;
    float av = a[r * D + d];
    float bv = fmaxf(b[r * D + d], 1e-8f);
    float w  = 0.70710678118654752f / bv;
    int p = r >> 1, e = r & 1;
    float* wv = reinterpret_cast<float*>(&gWV4[d * 64 + p]);
    wv[e]     = w;
    wv[2 + e] = -w * av;
    reinterpret_cast<float*>(&gC2[d * 64 + p])[e] = c[r * (D + 1) + d];
    if (d == 0)
        reinterpret_cast<float*>(&gB2[p])[e] = c[r * (D + 1) + D];
}

__device__ __forceinline__ ull fma2(ull a, ull b, ull c) {
    ull d;
    asm("fma.rn.f32x2 %0, %1, %2, %3;" : "=l"(d) : "l"(a), "l"(b), "l"(c));
    return d;
}
__device__ __forceinline__ ull add2(ull a, ull b) {
    ull d;
    asm("add.rn.f32x2 %0, %1, %2;" : "=l"(d) : "l"(a), "l"(b));
    return d;
}
#define LDG128I(ptr, imm, lo, hi) \
    asm volatile("ld.global.nc.v2.u64 {%0, %1}, [%2 + %3];" \
                 : "=l"(lo), "=l"(hi) : "l"(ptr), "n"(imm))
#define LDG64I(ptr, imm, v) \
    asm volatile("ld.global.nc.u64 %0, [%1 + %2];" : "=l"(v) : "l"(ptr), "n"(imm))
#define LDS128I(base, imm, lo, hi) \
    asm volatile("ld.shared.v2.u64 {%0, %1}, [%2 + %3];" \
                 : "=l"(lo), "=l"(hi) : "r"(base), "n"(imm))
__device__ __forceinline__ void sts64(uint32_t addr, float lo, float hi) {
    asm volatile("st.shared.v2.f32 [%0], {%1, %2};" :: "r"(addr), "f"(lo), "f"(hi));
}
__device__ __forceinline__ void sts128(uint32_t addr, ull lo, ull hi) {
    asm volatile("st.shared.v2.u64 [%0], {%1, %2};" :: "r"(addr), "l"(lo), "l"(hi));
}
__device__ __forceinline__ void unpack2(ull v, float& lo, float& hi) {
    asm("mov.b64 {%0, %1}, %2;" : "=f"(lo), "=f"(hi) : "l"(v));
}
__device__ __forceinline__ ull pack2(float lo, float hi) {
    ull v;
    asm("mov.b64 %0, {%1, %2};" : "=l"(v) : "f"(lo), "f"(hi));
    return v;
}
__device__ __forceinline__ ull shfl2(ull v, int off) {
    return __shfl_xor_sync(0xffffffffu, v, off);
}

// smem: xt [2 ssets][32 d][8 samples] dup ull (4096B) + red [2][2][4][16B] (256B)
#define OFF_RED 4096

// one d: 1 LDG.128 + 1 LDG.64 + 4 broadcast LDS.128 + 24 fma2
#define STEPD(d)                                                              \
    {                                                                         \
        ull ww, vv, cc, xa, xc, u;                                            \
        LDG128I(wvp, (d) * 1024, ww, vv);                                     \
        LDG64I(ccp, (d) * 512, cc);                                           \
        LDS128I(xB, (d) * 64 + 0, xa, xc);                                    \
        u = fma2(ww, xa, vv); ag0 = fma2(u, u, ag0); al0 = fma2(cc, xa, al0); \
        u = fma2(ww, xc, vv); ag1 = fma2(u, u, ag1); al1 = fma2(cc, xc, al1); \
        LDS128I(xB, (d) * 64 + 16, xa, xc);                                   \
        u = fma2(ww, xa, vv); ag2 = fma2(u, u, ag2); al2 = fma2(cc, xa, al2); \
        u = fma2(ww, xc, vv); ag3 = fma2(u, u, ag3); al3 = fma2(cc, xc, al3); \
        LDS128I(xB, (d) * 64 + 32, xa, xc);                                   \
        u = fma2(ww, xa, vv); ag4 = fma2(u, u, ag4); al4 = fma2(cc, xa, al4); \
        u = fma2(ww, xc, vv); ag5 = fma2(u, u, ag5); al5 = fma2(cc, xc, al5); \
        LDS128I(xB, (d) * 64 + 48, xa, xc);                                   \
        u = fma2(ww, xa, vv); ag6 = fma2(u, u, ag6); al6 = fma2(cc, xa, al6); \
        u = fma2(ww, xc, vv); ag7 = fma2(u, u, ag7); al7 = fma2(cc, xc, al7); \
    }

// samples 2i, 2i+1: exp, strengths STG.64, pack (ss,ss') and (pp,pp') pairs
#define EPI2(i, AGa, ALa, AGb, ALb)                                           \
    ull ssq##i, ppq##i;                                                       \
    {                                                                         \
        float e0, e1, f0, f1, r0, r1, q0, q1;                                 \
        unpack2(AGa, e0, e1); unpack2(AGb, f0, f1);                           \
        float sa0 = __expf(-e0), sa1 = __expf(-e1);                           \
        float sb0 = __expf(-f0), sb1 = __expf(-f1);                           \
        unpack2(ALa, r0, r1); unpack2(ALb, q0, q1);                           \
        *reinterpret_cast<float2*>(&strengths[(n0 + 2 * (i)) * R + rb]) =     \
            make_float2(sa0, sa1);                                            \
        *reinterpret_cast<float2*>(&strengths[(n0 + 2 * (i) + 1) * R + rb]) = \
            make_float2(sb0, sb1);                                            \
        ssq##i = pack2(sa0 + sa1, sb0 + sb1);                                 \
        ppq##i = pack2(sa0 * r0 + sa1 * r1, sb0 * q0 + sb1 * q1);             \
        AGa = pack2(sa0, sa1);                                                \
        AGb = pack2(sb0, sb1);                                                \
    }

#define FIN2(i, AGa, AGb)                                                     \
    {                                                                         \
        ull sA, pA, sB, pB;                                                   \
        LDS128I(redR, 0 * 64 + (i) * 16, sA, pA);                             \
        LDS128I(redR, 1 * 64 + (i) * 16, sB, pB);                             \
        ull st = add2(sA, sB), pt = add2(pA, pB);                             \
        float ta, tb;                                                         \
        unpack2(st, ta, tb);                                                  \
        float inva = 1.0f / (ta + 1e-8f);                                     \
        float invb = 1.0f / (tb + 1e-8f);                                     \
        float s0, s1;                                                         \
        unpack2(AGa, s0, s1);                                                 \
        *reinterpret_cast<float2*>(&normalized[(n0 + 2 * (i)) * R + rb]) =    \
            make_float2(s0 * inva, s1 * inva);                                \
        unpack2(AGb, s0, s1);                                                 \
        *reinterpret_cast<float2*>(&normalized[(n0 + 2 * (i) + 1) * R + rb]) =\
            make_float2(s0 * invb, s1 * invb);                                \
        if (half == 0 && lane == 0) {                                         \
            float pa, pb;                                                     \
            unpack2(pt, pa, pb);                                              \
            *reinterpret_cast<float2*>(&pred[n0 + 2 * (i)]) =                 \
                make_float2(pa * inva, pb * invb);                            \
        }                                                                     \
    }

__global__ void __launch_bounds__(128, 8)
anfis_main(const float* __restrict__ X,
           float* __restrict__ pred,
           float* __restrict__ strengths,
           float* __restrict__ normalized) {
    __shared__ float smem[(4096 + 256) / 4];
    uint32_t sbase;
    {
        uint64_t t;
        asm("cvta.to.shared.u64 %0, %1;" : "=l"(t) : "l"(smem));
        sbase = (uint32_t)t;
    }

    // stage 16 samples, duplicated (x,x): xt[sset][d][s]; 128 threads, 1 float4 each
    {
        int t    = threadIdx.x;
        int sst  = t >> 6;
        int j    = t & 63;
        int row  = j >> 3;               // sample within octet
        int seg  = j & 7;                // float4 along D
        int n    = blockIdx.x * 16 + sst * 8 + row;
        float4 v = *reinterpret_cast<const float4*>(X + n * D + seg * 4);
        uint32_t base = sbase + sst * 2048 + ((seg * 4) * 8 + row) * 8;
        sts64(base + 0 * 64, v.x, v.x);
        sts64(base + 1 * 64, v.y, v.y);
        sts64(base + 2 * 64, v.z, v.z);
        sts64(base + 3 * 64, v.w, v.w);
    }
    __syncthreads();

    const int lane = threadIdx.x & 31;
    const int warp = threadIdx.x >> 5;
    const int sset = warp >> 1;          // sample octet
    const int half = warp & 1;           // rule half
    const int rb   = half * 64 + lane * 2;
    const int n0   = blockIdx.x * 16 + sset * 8;

    const float4* wvp = gWV4 + (half * 32 + lane);   // 16B record, d-stride 1024B
    const float2* ccp = gC2 + (half * 32 + lane);    //  8B record, d-stride 512B
    const uint32_t xB   = sbase + sset * 2048;
    const uint32_t redW = sbase + OFF_RED + (sset * 2 + half) * 64;
    const uint32_t redR = sbase + OFF_RED + sset * 128;

    ull bias2;
    LDG64I(gB2 + (half * 32 + lane), 0, bias2);

    ull ag0 = 0, ag1 = 0, ag2 = 0, ag3 = 0, ag4 = 0, ag5 = 0, ag6 = 0, ag7 = 0;
    ull al0 = bias2, al1 = bias2, al2 = bias2, al3 = bias2;
    ull al4 = bias2, al5 = bias2, al6 = bias2, al7 = bias2;

    STEPD(0)  STEPD(1)  STEPD(2)  STEPD(3)  STEPD(4)  STEPD(5)  STEPD(6)  STEPD(7)
    STEPD(8)  STEPD(9)  STEPD(10) STEPD(11) STEPD(12) STEPD(13) STEPD(14) STEPD(15)
    STEPD(16) STEPD(17) STEPD(18) STEPD(19) STEPD(20) STEPD(21) STEPD(22) STEPD(23)
    STEPD(24) STEPD(25) STEPD(26) STEPD(27) STEPD(28) STEPD(29) STEPD(30) STEPD(31)

    EPI2(0, ag0, al0, ag1, al1)
    EPI2(1, ag2, al2, ag3, al3)
    EPI2(2, ag4, al4, ag5, al5)
    EPI2(3, ag6, al6, ag7, al7)

    #pragma unroll
    for (int off = 16; off > 0; off >>= 1) {
        ssq0 = add2(ssq0, shfl2(ssq0, off)); ppq0 = add2(ppq0, shfl2(ppq0, off));
        ssq1 = add2(ssq1, shfl2(ssq1, off)); ppq1 = add2(ppq1, shfl2(ppq1, off));
        ssq2 = add2(ssq2, shfl2(ssq2, off)); ppq2 = add2(ppq2, shfl2(ppq2, off));
        ssq3 = add2(ssq3, shfl2(ssq3, off)); ppq3 = add2(ppq3, shfl2(ppq3, off));
    }
    if (lane == 0) {
        sts128(redW + 0,  ssq0, ppq0);
        sts128(redW + 16, ssq1, ppq1);
        sts128(redW + 32, ssq2, ppq2);
        sts128(redW + 48, ssq3, ppq3);
    }
    __syncthreads();

    FIN2(0, ag0, ag1)
    FIN2(1, ag2, ag3)
    FIN2(2, ag4, ag5)
    FIN2(3, ag6, ag7)
}

extern "C" void kernel_launch(void* const* d_in, const int* in_sizes, int n_in,
                              void* d_out, int out_size) {
    const float* X = (const float*)d_in[0];
    const float* a = (const float*)d_in[1];
    const float* b = (const float*)d_in[2];
    const float* c = (const float*)d_in[3];

    float* out        = (float*)d_out;
    float* pred       = out;
    float* strengths  = out + NS;
    float* normalized = out + NS + NS * R;

    anfis_precomp<<<R, D>>>(a, b, c);
    anfis_main<<<NS / 16, 128>>>(X, pred, strengths, normalized);
}

// round 16
// speedup vs baseline: 1.5422x; 1.5422x over previous
#include <cuda_runtime.h>
#include <cstdint>

#define NS 65536
#define D  32
#define R  128

typedef unsigned long long ull;

// transposed tables behind ONE base pointer: W @0, V @+16384B, C @+32768B
__device__ float gTab[3 * D * R];
__device__ float gBias[R];

__global__ void anfis_precomp(const float* __restrict__ a,
                              const float* __restrict__ b,
                              const float* __restrict__ c) {
    int r = blockIdx.x, d = threadIdx.x;
    float av = a[r * D + d];
    float bv = fmaxf(b[r * D + d], 1e-8f);
    float w  = 0.70710678118654752f / bv;
    gTab[d * R + r]        = w;                    // W
    gTab[4096 + d * R + r] = -w * av;              // V
    gTab[8192 + d * R + r] = c[r * (D + 1) + d];   // C
    if (d == 0) gBias[r] = c[r * (D + 1) + D];
}

__device__ __forceinline__ ull fma2(ull a, ull b, ull c) {
    ull d;
    asm("fma.rn.f32x2 %0, %1, %2, %3;" : "=l"(d) : "l"(a), "l"(b), "l"(c));
    return d;
}
__device__ __forceinline__ ull add2(ull a, ull b) {
    ull d;
    asm("add.rn.f32x2 %0, %1, %2;" : "=l"(d) : "l"(a), "l"(b));
    return d;
}
__device__ __forceinline__ ull mul2(ull a, ull b) {
    ull d;
    asm("mul.rn.f32x2 %0, %1, %2;" : "=l"(d) : "l"(a), "l"(b));
    return d;
}
#define LDGF(ptr, imm, f) \
    asm volatile("ld.global.nc.f32 %0, [%1 + %2];" : "=f"(f) : "l"(ptr), "n"(imm))
#define LDS128I(base, imm, lo, hi) \
    asm volatile("ld.shared.v2.u64 {%0, %1}, [%2 + %3];" \
                 : "=l"(lo), "=l"(hi) : "r"(base), "n"(imm))
__device__ __forceinline__ void sts128(uint32_t addr, ull lo, ull hi) {
    asm volatile("st.shared.v2.u64 [%0], {%1, %2};" :: "r"(addr), "l"(lo), "l"(hi));
}
__device__ __forceinline__ void unpack2(ull v, float& lo, float& hi) {
    asm("mov.b64 {%0, %1}, %2;" : "=f"(lo), "=f"(hi) : "l"(v));
}
__device__ __forceinline__ ull pack2(float lo, float hi) {
    ull v;
    asm("mov.b64 %0, {%1, %2};" : "=l"(v) : "f"(lo), "f"(hi));
    return v;
}
__device__ __forceinline__ ull shfl2(ull v, int off) {
    return __shfl_xor_sync(0xffffffffu, v, off);
}

// smem: xt[32 d][16 samples] f32 (2048B) + red[8 pairs][4 warps][16B] (512B)
#define OFF_RED 2048

// one d: 3 LDG.32 + 3 packs + 4 broadcast LDS.128 (16 samples) + 24 fma2
#define STEPD(d)                                                              \
    {                                                                         \
        float w, v, cc;                                                       \
        LDGF(cb, (d) * 512, w);                                               \
        LDGF(cb, (d) * 512 + 16384, v);                                       \
        LDGF(cb, (d) * 512 + 32768, cc);                                      \
        ull w2 = pack2(w, w), v2 = pack2(v, v), c2 = pack2(cc, cc);           \
        ull xa, xq, u;                                                        \
        LDS128I(xB, (d) * 64 + 0, xa, xq);                                    \
        u = fma2(w2, xa, v2); ag0 = fma2(u, u, ag0); al0 = fma2(c2, xa, al0); \
        u = fma2(w2, xq, v2); ag1 = fma2(u, u, ag1); al1 = fma2(c2, xq, al1); \
        LDS128I(xB, (d) * 64 + 16, xa, xq);                                   \
        u = fma2(w2, xa, v2); ag2 = fma2(u, u, ag2); al2 = fma2(c2, xa, al2); \
        u = fma2(w2, xq, v2); ag3 = fma2(u, u, ag3); al3 = fma2(c2, xq, al3); \
        LDS128I(xB, (d) * 64 + 32, xa, xq);                                   \
        u = fma2(w2, xa, v2); ag4 = fma2(u, u, ag4); al4 = fma2(c2, xa, al4); \
        u = fma2(w2, xq, v2); ag5 = fma2(u, u, ag5); al5 = fma2(c2, xq, al5); \
        LDS128I(xB, (d) * 64 + 48, xa, xq);                                   \
        u = fma2(w2, xa, v2); ag6 = fma2(u, u, ag6); al6 = fma2(c2, xa, al6); \
        u = fma2(w2, xq, v2); ag7 = fma2(u, u, ag7); al7 = fma2(c2, xq, al7); \
    }

// pair i = samples (n0+2i, n0+2i+1): exp, strengths, reduce, stash
#define EPI(i, AG, AL)                                                        \
    {                                                                         \
        float e0, e1;                                                         \
        unpack2(AG, e0, e1);                                                  \
        float s0 = __expf(-e0), s1 = __expf(-e1);                             \
        ull s2 = pack2(s0, s1);                                               \
        strengths[(n0 + 2 * (i))     * R + r] = s0;                           \
        strengths[(n0 + 2 * (i) + 1) * R + r] = s1;                           \
        ull pp2 = mul2(s2, AL);                                               \
        ull ss2 = s2;                                                         \
        _Pragma("unroll")                                                     \
        for (int off = 16; off > 0; off >>= 1) {                              \
            ss2 = add2(ss2, shfl2(ss2, off));                                 \
            pp2 = add2(pp2, shfl2(pp2, off));                                 \
        }                                                                     \
        if (lane == 0) sts128(redB + (i) * 64 + q * 16, ss2, pp2);            \
        AG = s2;                                                              \
    }

#define FIN(i, AG)                                                            \
    {                                                                         \
        ull s01, p01, s23, p23, s45, p45, s67, p67;                           \
        LDS128I(redB, (i) * 64 + 0,  s01, p01);                               \
        LDS128I(redB, (i) * 64 + 16, s23, p23);                               \
        LDS128I(redB, (i) * 64 + 32, s45, p45);                               \
        LDS128I(redB, (i) * 64 + 48, s67, p67);                               \
        ull sst = add2(add2(s01, s23), add2(s45, s67));                       \
        ull ppt = add2(add2(p01, p23), add2(p45, p67));                       \
        float ta, tb;                                                         \
        unpack2(sst, ta, tb);                                                 \
        float inva = 1.0f / (ta + 1e-8f);                                     \
        float invb = 1.0f / (tb + 1e-8f);                                     \
        float s0, s1;                                                         \
        unpack2(AG, s0, s1);                                                  \
        normalized[(n0 + 2 * (i))     * R + r] = s0 * inva;                   \
        normalized[(n0 + 2 * (i) + 1) * R + r] = s1 * invb;                   \
        if (q == 0 && lane == 0) {                                            \
            float pa, pb;                                                     \
            unpack2(ppt, pa, pb);                                             \
            *reinterpret_cast<float2*>(&pred[n0 + 2 * (i)]) =                 \
                make_float2(pa * inva, pb * invb);                            \
        }                                                                     \
    }

__global__ void __launch_bounds__(128, 7)
anfis_main(const float* __restrict__ X,
           float* __restrict__ pred,
           float* __restrict__ strengths,
           float* __restrict__ normalized) {
    __shared__ float smem[(2048 + 512) / 4];
    uint32_t sbase;
    {
        uint64_t t;
        asm("cvta.to.shared.u64 %0, %1;" : "=l"(t) : "l"(smem));
        sbase = (uint32_t)t;
    }

    const int n0 = blockIdx.x * 16;     // 16 samples per block

    // stage X transposed, NO duplication: xt[d][s]; 128 threads, one float4 each
    {
        int row = threadIdx.x >> 3;     // sample 0..15
        int seg = threadIdx.x & 7;      // float4 along D
        float4 v = *reinterpret_cast<const float4*>(X + (n0 + row) * D + seg * 4);
        smem[(seg * 4 + 0) * 16 + row] = v.x;
        smem[(seg * 4 + 1) * 16 + row] = v.y;
        smem[(seg * 4 + 2) * 16 + row] = v.z;
        smem[(seg * 4 + 3) * 16 + row] = v.w;
    }
    __syncthreads();

    const int lane = threadIdx.x & 31;
    const int q    = threadIdx.x >> 5;   // warp = rule quarter
    const int r    = q * 32 + lane;      // this lane's rule

    const float* cb = gTab + r;          // +d*512B; V +16384B; C +32768B
    const uint32_t xB   = sbase;
    const uint32_t redB = sbase + OFF_RED;

    // bias folded into consequent accumulators
    float biasf;
    asm volatile("ld.global.nc.f32 %0, [%1];" : "=f"(biasf) : "l"(gBias + r));
    const ull bias2 = pack2(biasf, biasf);

    ull ag0 = 0, ag1 = 0, ag2 = 0, ag3 = 0, ag4 = 0, ag5 = 0, ag6 = 0, ag7 = 0;
    ull al0 = bias2, al1 = bias2, al2 = bias2, al3 = bias2;
    ull al4 = bias2, al5 = bias2, al6 = bias2, al7 = bias2;

    STEPD(0)  STEPD(1)  STEPD(2)  STEPD(3)  STEPD(4)  STEPD(5)  STEPD(6)  STEPD(7)
    STEPD(8)  STEPD(9)  STEPD(10) STEPD(11) STEPD(12) STEPD(13) STEPD(14) STEPD(15)
    STEPD(16) STEPD(17) STEPD(18) STEPD(19) STEPD(20) STEPD(21) STEPD(22) STEPD(23)
    STEPD(24) STEPD(25) STEPD(26) STEPD(27) STEPD(28) STEPD(29) STEPD(30) STEPD(31)

    EPI(0, ag0, al0) EPI(1, ag1, al1) EPI(2, ag2, al2) EPI(3, ag3, al3)
    EPI(4, ag4, al4) EPI(5, ag5, al5) EPI(6, ag6, al6) EPI(7, ag7, al7)
    __syncthreads();
    FIN(0, ag0) FIN(1, ag1) FIN(2, ag2) FIN(3, ag3)
    FIN(4, ag4) FIN(5, ag5) FIN(6, ag6) FIN(7, ag7)
}

extern "C" void kernel_launch(void* const* d_in, const int* in_sizes, int n_in,
                              void* d_out, int out_size) {
    const float* X = (const float*)d_in[0];
    const float* a = (const float*)d_in[1];
    const float* b = (const float*)d_in[2];
    const float* c = (const float*)d_in[3];

    float* out        = (float*)d_out;
    float* pred       = out;
    float* strengths  = out + NS;
    float* normalized = out + NS + NS * R;

    anfis_precomp<<<R, D>>>(a, b, c);
    anfis_main<<<NS / 16, 128>>>(X, pred, strengths, normalized);
}